// round 1
// baseline (speedup 1.0000x reference)
#include <cuda_runtime.h>
#include <math.h>

// Problem constants
#define B_   8
#define C_   128
#define N_   4096
#define K_   32
#define O_   64
#define NH_  80            // 64 trans + 8 gate + 8 attn combined output rows
#define TN_  4             // n-rows per block
#define M_   (TN_ * K_)    // 128 positions per block

#define YS_STRIDE 81       // odd-ish stride: bank = (17*m + o) % 32 -> conflict-free
#define SMEM_FLOATS (16384 + 10240 + 128)   // Xs/Ys union + Ws + WF
#define SMEM_BYTES  (SMEM_FLOATS * 4)       // 107008 B -> 2 blocks/SM

typedef unsigned long long u64;

// -------- packed f32x2 helpers (Blackwell FFMA2 path) --------
__device__ __forceinline__ u64 pack_dup(float x) {
    u64 r;
    asm("mov.b64 %0, {%1, %1};" : "=l"(r) : "f"(x));
    return r;
}
__device__ __forceinline__ void fma2(u64 &d, u64 a, u64 b) {
    asm("fma.rn.f32x2 %0, %1, %2, %0;" : "+l"(d) : "l"(a), "l"(b));
}
__device__ __forceinline__ void unpack2(u64 v, float &lo, float &hi) {
    asm("mov.b64 {%0, %1}, %2;" : "=f"(lo), "=f"(hi) : "l"(v));
}

// Transposed combined weight matrix Wt[c][o], o in [0,80)
__device__ float g_Wt[C_ * NH_];

__global__ void prep_w_kernel(const float* __restrict__ w_trans,
                              const float* __restrict__ w_gate1,
                              const float* __restrict__ w_attn1) {
    int idx = blockIdx.x * blockDim.x + threadIdx.x;
    if (idx >= C_ * NH_) return;
    int c = idx / NH_;
    int o = idx - c * NH_;
    float v;
    if (o < 64)      v = w_trans[o * C_ + c];
    else if (o < 72) v = w_gate1[(o - 64) * C_ + c];
    else             v = w_attn1[(o - 72) * C_ + c];
    g_Wt[idx] = v;
}

__global__ __launch_bounds__(256, 2)
void gsl_kernel(const float* __restrict__ x,
                const float* __restrict__ g_trans, const float* __restrict__ b_trans,
                const float* __restrict__ g_gate,  const float* __restrict__ b_gate,
                const float* __restrict__ w_gate2, const float* __restrict__ b_gate2,
                const float* __restrict__ g_attn,  const float* __restrict__ b_attn,
                const float* __restrict__ w_attn2, const float* __restrict__ b_attn2,
                const float* __restrict__ agg_alpha,
                float* __restrict__ out, float* __restrict__ gate_out)
{
    extern __shared__ float smem[];
    float* Xs = smem;              // [128][128] input tile (later reused as Ys [128][81])
    float* Ws = smem + 16384;      // [128][80]  transposed weights
    float* WF = smem + 16384 + 10240; // [128] final softmax weights

    const int t   = threadIdx.x;
    const int blk = blockIdx.x;
    const int b   = blk >> 10;            // blk / 1024
    const int nb  = (blk & 1023) * TN_;   // base n

    // ---- load weights (coalesced read + conflict-free smem write) ----
    #pragma unroll
    for (int it = 0; it < (C_ * NH_) / 256; it++)
        Ws[t + it * 256] = g_Wt[t + it * 256];

    // ---- load x tile: 128 rows (c) x 128 floats (4n x 32k contiguous) ----
    {
        const int xbase = (b * C_) * (N_ * K_) + nb * K_;  // fits in int (max ~134M)
        #pragma unroll
        for (int it = 0; it < 16; it++) {
            int idx = t + it * 256;
            int c = idx >> 5;          // /32
            int q = idx & 31;          // float4 index within row
            float4 v = *reinterpret_cast<const float4*>(x + xbase + c * (N_ * K_) + q * 4);
            *reinterpret_cast<float4*>(&Xs[c * 128 + q * 4]) = v;
        }
    }
    __syncthreads();

    // ---- GEMM: Y[80][128] = W[80][128] * X[128][128], packed f32x2 over o-pairs ----
    const int tx = t & 31;     // m sub-index (lane-consecutive x loads)
    const int ty = t >> 5;     // 0..7 -> 10 o's each
    const int oB = ty * 10;

    u64 acc[5][4];
    #pragma unroll
    for (int i = 0; i < 5; i++)
        #pragma unroll
        for (int j = 0; j < 4; j++) acc[i][j] = 0ull;

    #pragma unroll 2
    for (int c = 0; c < C_; c++) {
        const float* xr = Xs + c * 128 + tx;
        u64 xd[4];
        #pragma unroll
        for (int j = 0; j < 4; j++) xd[j] = pack_dup(xr[32 * j]);
        const float* wr = Ws + c * NH_ + oB;
        #pragma unroll
        for (int i = 0; i < 5; i++) {
            u64 wp = *reinterpret_cast<const u64*>(wr + 2 * i);   // (w[o], w[o+1])
            #pragma unroll
            for (int j = 0; j < 4; j++) fma2(acc[i][j], wp, xd[j]);
        }
    }
    __syncthreads();   // all Xs reads done; safe to overwrite with Ys

    // ---- scatter Y to smem as Ys[m][o], stride 81 (conflict-free) ----
    float* Ys = smem;
    #pragma unroll
    for (int i = 0; i < 5; i++) {
        #pragma unroll
        for (int j = 0; j < 4; j++) {
            float lo, hi;
            unpack2(acc[i][j], lo, hi);
            int m = tx + 32 * j;
            Ys[m * YS_STRIDE + oB + 2 * i]     = lo;
            Ys[m * YS_STRIDE + oB + 2 * i + 1] = hi;
        }
    }
    __syncthreads();

    const float alpha = 1.0f / (1.0f + __expf(-agg_alpha[0]));

    // ---- phase A+B: heads + masked softmax (one warp per n-row, lane = k) ----
    if (t < M_) {
        const int m = t;
        float gl = b_gate2[0];
        float al = b_attn2[0];
        #pragma unroll
        for (int h = 0; h < 8; h++) {
            float yg = Ys[m * YS_STRIDE + 64 + h];
            float v  = fmaf(g_gate[h], yg, b_gate[h]);
            v = (v >= 0.0f) ? v : 0.2f * v;
            gl = fmaf(w_gate2[h], v, gl);
            float ya = Ys[m * YS_STRIDE + 72 + h];
            float u  = fmaf(g_attn[h], ya, b_attn[h]);
            u = (u >= 0.0f) ? u : 0.2f * u;
            al = fmaf(w_attn2[h], u, al);
        }
        // gate_logits output [B,1,N,K]
        gate_out[b * (N_ * K_) + nb * K_ + m] = gl;

        // softmax over k (warp-wide), then mask + renormalize
        float amax = al;
        #pragma unroll
        for (int s = 16; s > 0; s >>= 1)
            amax = fmaxf(amax, __shfl_xor_sync(0xffffffffu, amax, s));
        float e = __expf(al - amax);
        float S = e;
        #pragma unroll
        for (int s = 16; s > 0; s >>= 1)
            S += __shfl_xor_sync(0xffffffffu, S, s);
        float w  = e / S;
        float wm = (gl >= 0.0f) ? w : 0.0f;
        float Sm = wm;
        #pragma unroll
        for (int s = 16; s > 0; s >>= 1)
            Sm += __shfl_xor_sync(0xffffffffu, Sm, s);
        WF[m] = wm / (Sm + 1e-6f);
    }
    __syncthreads();

    // ---- phase C: trans_feat affine+lrelu, weighted sum + max over k ----
    {
        const int o = t & 63;
        const int n = t >> 6;
        const float g  = g_trans[o];
        const float bb = b_trans[o];
        const int mBase = n * K_;
        float s  = 0.0f;
        float mx = -INFINITY;
        #pragma unroll
        for (int k = 0; k < K_; k++) {
            float y  = Ys[(mBase + k) * YS_STRIDE + o];
            float tv = fmaf(g, y, bb);
            tv = (tv >= 0.0f) ? tv : 0.2f * tv;
            s  = fmaf(tv, WF[mBase + k], s);
            mx = fmaxf(mx, tv);
        }
        out[(b * O_ + o) * N_ + nb + n] = alpha * s + (1.0f - alpha) * mx;
    }
}

extern "C" void kernel_launch(void* const* d_in, const int* in_sizes, int n_in,
                              void* d_out, int out_size) {
    const float* x        = (const float*)d_in[0];
    const float* w_trans  = (const float*)d_in[1];
    const float* g_trans  = (const float*)d_in[2];
    const float* b_trans  = (const float*)d_in[3];
    const float* w_gate1  = (const float*)d_in[4];
    const float* g_gate   = (const float*)d_in[5];
    const float* b_gate   = (const float*)d_in[6];
    const float* w_gate2  = (const float*)d_in[7];
    const float* b_gate2  = (const float*)d_in[8];
    const float* w_attn1  = (const float*)d_in[9];
    const float* g_attn   = (const float*)d_in[10];
    const float* b_attn   = (const float*)d_in[11];
    const float* w_attn2  = (const float*)d_in[12];
    const float* b_attn2  = (const float*)d_in[13];
    const float* agg_alpha= (const float*)d_in[14];

    float* out      = (float*)d_out;                     // [B,O,N] = 2,097,152 floats
    float* gate_out = out + (size_t)B_ * O_ * N_;        // [B,1,N,K] = 1,048,576 floats

    cudaFuncSetAttribute(gsl_kernel, cudaFuncAttributeMaxDynamicSharedMemorySize, SMEM_BYTES);

    prep_w_kernel<<<(C_ * NH_ + 255) / 256, 256>>>(w_trans, w_gate1, w_attn1);
    gsl_kernel<<<B_ * (N_ / TN_), 256, SMEM_BYTES>>>(
        x, g_trans, b_trans, g_gate, b_gate, w_gate2, b_gate2,
        g_attn, b_attn, w_attn2, b_attn2, agg_alpha, out, gate_out);
}

// round 3
// speedup vs baseline: 1.9155x; 1.9155x over previous
#include <cuda_runtime.h>
#include <cuda_bf16.h>
#include <cstdint>
#include <math.h>

#define B_   8
#define N_   4096
#define K_   32
#define C_   128
#define O_   64
#define NH_  80
#define TN_  4
#define M_   128

// ---- smem layout (bytes) ----
#define SM_WHI  0          // 80x128 bf16 swizzled image
#define SM_WLO  20480
#define SM_XHI  40960      // 128c x 128m bf16 swizzled
#define SM_XLO  73728
#define SM_WF   106496     // 128 floats
#define SM_OBUF 107008     // 64x4 floats
#define SM_TOTAL 108032
#define SM_YS   40960      // overlay on X region: 128 x 81 floats = 41472B
#define YS_STRIDE 81

__device__ __forceinline__ uint32_t smem_u32(const void* p) {
    uint32_t a;
    asm("{ .reg .u64 t; cvta.to.shared.u64 t, %1; cvt.u32.u64 %0, t; }" : "=r"(a) : "l"(p));
    return a;
}

#define LDSM_X4(r, a) \
    asm volatile("ldmatrix.sync.aligned.m8n8.x4.shared.b16 {%0,%1,%2,%3}, [%4];" \
        : "=r"((r)[0]), "=r"((r)[1]), "=r"((r)[2]), "=r"((r)[3]) : "r"(a))
#define LDSM_X4_T(r, a) \
    asm volatile("ldmatrix.sync.aligned.m8n8.x4.trans.shared.b16 {%0,%1,%2,%3}, [%4];" \
        : "=r"((r)[0]), "=r"((r)[1]), "=r"((r)[2]), "=r"((r)[3]) : "r"(a))
#define MMA_BF16(c, a, b0, b1) \
    asm volatile("mma.sync.aligned.m16n8k16.row.col.f32.bf16.bf16.f32 " \
        "{%0,%1,%2,%3},{%4,%5,%6,%7},{%8,%9},{%0,%1,%2,%3};" \
        : "+f"((c)[0]), "+f"((c)[1]), "+f"((c)[2]), "+f"((c)[3]) \
        : "r"((a)[0]), "r"((a)[1]), "r"((a)[2]), "r"((a)[3]), "r"(b0), "r"(b1))

__device__ __forceinline__ uint32_t pack_bf2(float a, float b) {
    __nv_bfloat162 h = __floats2bfloat162_rn(a, b);   // .x = a (low half)
    return *reinterpret_cast<uint32_t*>(&h);
}

// ================= weight prep =================
// Combined W[80][128] -> bf16 hi/lo, swizzled ldmatrix image:
// byte(o,c) = o*256 + (((c>>3) ^ (o&7)) << 4) + (c&7)*2
__device__ uint4 g_Wimg[2560];   // 40960 B: [0:20480)=hi, [20480:40960)=lo

__global__ void prep_b(const float* __restrict__ wt, const float* __restrict__ wg,
                       const float* __restrict__ wa) {
    int i = blockIdx.x * blockDim.x + threadIdx.x;
    if (i >= NH_ * C_) return;
    int o = i >> 7, c = i & 127;
    float w = (o < 64) ? wt[o * C_ + c]
            : (o < 72) ? wg[(o - 64) * C_ + c]
                       : wa[(o - 72) * C_ + c];
    __nv_bfloat16 h = __float2bfloat16(w);
    __nv_bfloat16 l = __float2bfloat16(w - __bfloat162float(h));
    unsigned byte = (unsigned)o * 256u + ((((unsigned)(c >> 3) ^ (o & 7)) << 4)) + (c & 7) * 2u;
    __nv_bfloat16* base = (__nv_bfloat16*)g_Wimg;
    base[byte >> 1] = h;
    base[(20480u + byte) >> 1] = l;
}

// ================= main kernel =================
__global__ __launch_bounds__(256, 2)
void gsl_mma(const float* __restrict__ x,
             const float* __restrict__ g_trans, const float* __restrict__ b_trans,
             const float* __restrict__ g_gate,  const float* __restrict__ b_gate,
             const float* __restrict__ w_gate2, const float* __restrict__ b_gate2,
             const float* __restrict__ g_attn,  const float* __restrict__ b_attn,
             const float* __restrict__ w_attn2, const float* __restrict__ b_attn2,
             const float* __restrict__ agg_alpha,
             float* __restrict__ out, float* __restrict__ gate_out)
{
    extern __shared__ char smem[];
    const uint32_t sb = smem_u32(smem);
    const int t    = threadIdx.x;
    const int wid  = t >> 5;
    const int lane = t & 31;
    const int blk  = blockIdx.x;
    const int b    = blk >> 10;
    const int nb   = (blk & 1023) * TN_;

    // ---- copy weight images (40960 B) ----
    {
        uint4* d = (uint4*)smem;
        #pragma unroll
        for (int i = 0; i < 10; i++) d[t + 256 * i] = g_Wimg[t + 256 * i];
    }

    // ---- load x tile, convert to bf16 hi/lo planes (swizzled) ----
    {
        const int xbase = b * (C_ * N_ * K_) + nb * K_;
        char* Xhi = smem + SM_XHI;
        char* Xlo = smem + SM_XLO;
        #pragma unroll
        for (int it = 0; it < 16; it++) {
            int idx = t + it * 256;
            int c = idx >> 5, q = idx & 31;
            float4 v = *(const float4*)(x + xbase + c * (N_ * K_) + q * 4);
            __nv_bfloat16 h0 = __float2bfloat16(v.x);
            __nv_bfloat16 h1 = __float2bfloat16(v.y);
            __nv_bfloat16 h2 = __float2bfloat16(v.z);
            __nv_bfloat16 h3 = __float2bfloat16(v.w);
            uint2 ph, pl;
            ph.x = (uint32_t)__bfloat16_as_ushort(h0) | ((uint32_t)__bfloat16_as_ushort(h1) << 16);
            ph.y = (uint32_t)__bfloat16_as_ushort(h2) | ((uint32_t)__bfloat16_as_ushort(h3) << 16);
            pl.x = pack_bf2(v.x - __bfloat162float(h0), v.y - __bfloat162float(h1));
            pl.y = pack_bf2(v.z - __bfloat162float(h2), v.w - __bfloat162float(h3));
            unsigned off = (unsigned)c * 256u + ((((unsigned)(q >> 1)) ^ (c & 7)) << 4) + (q & 1) * 8u;
            *(uint2*)(Xhi + off) = ph;
            *(uint2*)(Xlo + off) = pl;
        }
    }
    __syncthreads();

    // ---- mainloop: D[128m][80n] = Whi*Xhi + Whi*Xlo + Wlo*Xhi ----
    const int l7   = lane & 7;
    const int koff = (lane >> 3) & 1;                 // +8 col group
    const int r16  = l7 + ((lane & 16) >> 1);         // row offset 0..15
    const uint32_t aHi = sb + SM_XHI + r16 * 256 + ((((unsigned)(2 * wid + koff)) ^ l7) << 4);
    const uint32_t aLo = aHi + (SM_XLO - SM_XHI);
    const uint32_t bRowHi = sb + SM_WHI + r16 * 256;
    const uint32_t bRowLo = sb + SM_WLO + r16 * 256;

    float acc[10][4];
    #pragma unroll
    for (int i = 0; i < 10; i++)
        #pragma unroll
        for (int j = 0; j < 4; j++) acc[i][j] = 0.0f;

    #pragma unroll
    for (int k = 0; k < 8; k++) {
        uint32_t ah[4], al[4];
        LDSM_X4_T(ah, aHi + k * 4096);
        LDSM_X4_T(al, aLo + k * 4096);
        const uint32_t cs = (((unsigned)(2 * k + koff)) ^ l7) << 4;
        #pragma unroll
        for (int jp = 0; jp < 5; jp++) {
            uint32_t bh[4], bl[4];
            LDSM_X4(bh, bRowHi + jp * 4096 + cs);
            LDSM_X4(bl, bRowLo + jp * 4096 + cs);
            MMA_BF16(acc[2 * jp],     ah, bh[0], bh[1]);
            MMA_BF16(acc[2 * jp + 1], ah, bh[2], bh[3]);
            MMA_BF16(acc[2 * jp],     al, bh[0], bh[1]);
            MMA_BF16(acc[2 * jp + 1], al, bh[2], bh[3]);
            MMA_BF16(acc[2 * jp],     ah, bl[0], bl[1]);
            MMA_BF16(acc[2 * jp + 1], ah, bl[2], bl[3]);
        }
    }
    __syncthreads();   // all ldmatrix reads done; X region can become Ys

    // ---- scatter accumulators to Ys[m][o] ----
    float* Ys = (float*)(smem + SM_YS);
    {
        const int m0 = wid * 16 + (lane >> 2);
        const int nb4 = 2 * (lane & 3);
        #pragma unroll
        for (int jj = 0; jj < 10; jj++) {
            const int n0 = 8 * jj + nb4;
            Ys[m0 * YS_STRIDE + n0]           = acc[jj][0];
            Ys[m0 * YS_STRIDE + n0 + 1]       = acc[jj][1];
            Ys[(m0 + 8) * YS_STRIDE + n0]     = acc[jj][2];
            Ys[(m0 + 8) * YS_STRIDE + n0 + 1] = acc[jj][3];
        }
    }
    __syncthreads();

    // ---- phase A+B: heads + masked softmax (one warp per n-row, lane = k) ----
    float* WF = (float*)(smem + SM_WF);
    if (t < M_) {
        const int m = t;
        float gl = b_gate2[0];
        float al = b_attn2[0];
        #pragma unroll
        for (int h = 0; h < 8; h++) {
            float yg = Ys[m * YS_STRIDE + 64 + h];
            float v  = fmaf(g_gate[h], yg, b_gate[h]);
            v = (v >= 0.0f) ? v : 0.2f * v;
            gl = fmaf(w_gate2[h], v, gl);
            float ya = Ys[m * YS_STRIDE + 72 + h];
            float u  = fmaf(g_attn[h], ya, b_attn[h]);
            u = (u >= 0.0f) ? u : 0.2f * u;
            al = fmaf(w_attn2[h], u, al);
        }
        gate_out[b * (N_ * K_) + nb * K_ + m] = gl;

        float amax = al;
        #pragma unroll
        for (int s = 16; s > 0; s >>= 1)
            amax = fmaxf(amax, __shfl_xor_sync(0xffffffffu, amax, s));
        float e = __expf(al - amax);
        float S = e;
        #pragma unroll
        for (int s = 16; s > 0; s >>= 1)
            S += __shfl_xor_sync(0xffffffffu, S, s);
        float w  = e / S;
        float wm = (gl >= 0.0f) ? w : 0.0f;
        float Sm = wm;
        #pragma unroll
        for (int s = 16; s > 0; s >>= 1)
            Sm += __shfl_xor_sync(0xffffffffu, Sm, s);
        WF[m] = wm / (Sm + 1e-6f);
    }
    __syncthreads();

    // ---- phase C: affine + lrelu, weighted sum + max over k ----
    const float alpha = 1.0f / (1.0f + __expf(-agg_alpha[0]));
    float* Obuf = (float*)(smem + SM_OBUF);
    {
        const int o = t & 63;
        const int n = t >> 6;
        const float g  = g_trans[o];
        const float bb = b_trans[o];
        const int mBase = n * K_;
        float s  = 0.0f;
        float mx = -INFINITY;
        #pragma unroll
        for (int k = 0; k < K_; k++) {
            float y  = Ys[(mBase + k) * YS_STRIDE + o];
            float tv = fmaf(g, y, bb);
            tv = (tv >= 0.0f) ? tv : 0.2f * tv;
            s  = fmaf(tv, WF[mBase + k], s);
            mx = fmaxf(mx, tv);
        }
        Obuf[o * 4 + n] = alpha * s + (1.0f - alpha) * mx;
    }
    __syncthreads();

    if (t < 64) {
        float4 v = *(float4*)(Obuf + t * 4);
        *(float4*)(out + (b * O_ + t) * N_ + nb) = v;
    }
}

extern "C" void kernel_launch(void* const* d_in, const int* in_sizes, int n_in,
                              void* d_out, int out_size) {
    const float* x        = (const float*)d_in[0];
    const float* w_trans  = (const float*)d_in[1];
    const float* g_trans  = (const float*)d_in[2];
    const float* b_trans  = (const float*)d_in[3];
    const float* w_gate1  = (const float*)d_in[4];
    const float* g_gate   = (const float*)d_in[5];
    const float* b_gate   = (const float*)d_in[6];
    const float* w_gate2  = (const float*)d_in[7];
    const float* b_gate2  = (const float*)d_in[8];
    const float* w_attn1  = (const float*)d_in[9];
    const float* g_attn   = (const float*)d_in[10];
    const float* b_attn   = (const float*)d_in[11];
    const float* w_attn2  = (const float*)d_in[12];
    const float* b_attn2  = (const float*)d_in[13];
    const float* agg_alpha= (const float*)d_in[14];

    float* out      = (float*)d_out;                  // [B,O,N]
    float* gate_out = out + (size_t)B_ * O_ * N_;     // [B,1,N,K]

    cudaFuncSetAttribute(gsl_mma, cudaFuncAttributeMaxDynamicSharedMemorySize, SM_TOTAL);

    prep_b<<<(NH_ * C_ + 255) / 256, 256>>>(w_trans, w_gate1, w_attn1);
    gsl_mma<<<B_ * (N_ / TN_), 256, SM_TOTAL>>>(
        x, g_trans, b_trans, g_gate, b_gate, w_gate2, b_gate2,
        g_attn, b_attn, w_attn2, b_attn2, agg_alpha, out, gate_out);
}